// round 17
// baseline (speedup 1.0000x reference)
#include <cuda_runtime.h>
#include <cuda.h>
#include <cstdint>

#define NN 2048
#define IN_DIM 1024
#define MLPW 16
#define HIDD 256
#define L2DIM 64
#define NCLS 4
#define NSPL 4

// ---------------- scratch (device globals; no allocation) ----------------
__device__ float g_A[(size_t)NN * NN];          // A = adj*mask + I (tf32-rounded)
__device__ float g_Xt[(size_t)NN * IN_DIM];     // tf32-rounded x [2048][1024]
__device__ float g_W12t[(size_t)L2DIM * IN_DIM];// tf32 (Wg1@Wl2)^T [64][1024]
__device__ float g_Yt[(size_t)L2DIM * NN];      // tf32 (dc ⊙ x@W12)^T [64][2048]
__device__ float g_Hp[NSPL][(size_t)NN * L2DIM];// A@Y split-K partials (fp32)
__device__ float g_HW[(size_t)NN * NCLS];       // dc-scaled hid@Wg2
__device__ float g_rowsum[NN];
__device__ float g_colsum[NN];   // zero at load (.bss); re-zeroed by out_kernel

__device__ __forceinline__ float rsqrt_pos(float v) {
    return v > 0.f ? rsqrtf(v) : 0.f;
}
__device__ __forceinline__ uint32_t f2tf32(float f) {
    uint32_t u;
    asm("cvt.rna.tf32.f32 %0, %1;" : "=r"(u) : "f"(f));
    return u;
}

// ---------------- TMA / mbarrier / ldmatrix helpers ------------------------
__device__ __forceinline__ void tma2d(uint32_t dst, const CUtensorMap* m,
                                      int x, int y, uint32_t bar) {
    asm volatile(
        "cp.async.bulk.tensor.2d.shared::cta.global.tile.mbarrier::complete_tx::bytes "
        "[%0], [%1, {%2, %3}], [%4];"
        :: "r"(dst), "l"(m), "r"(x), "r"(y), "r"(bar) : "memory");
}
__device__ __forceinline__ void mbar_init(uint32_t bar, uint32_t cnt) {
    asm volatile("mbarrier.init.shared.b64 [%0], %1;" :: "r"(bar), "r"(cnt) : "memory");
}
__device__ __forceinline__ void mbar_expect_tx(uint32_t bar, uint32_t bytes) {
    asm volatile("mbarrier.arrive.expect_tx.shared.b64 _, [%0], %1;"
                 :: "r"(bar), "r"(bytes) : "memory");
}
__device__ __forceinline__ void mbar_wait(uint32_t bar, uint32_t parity) {
    uint32_t done;
    asm volatile(
        "{\n\t.reg .pred p;\n\t"
        "mbarrier.try_wait.parity.acquire.cta.shared::cta.b64 p, [%1], %2;\n\t"
        "selp.b32 %0, 1, 0, p;\n\t}"
        : "=r"(done) : "r"(bar), "r"(parity) : "memory");
    if (!done) {
        asm volatile(
            "{\n\t.reg .pred P1;\n\t"
            "WL_%=:\n\t"
            "mbarrier.try_wait.parity.acquire.cta.shared::cta.b64 P1, [%0], %1, 0x989680;\n\t"
            "@P1 bra.uni WD_%=;\n\t"
            "bra.uni WL_%=;\n\t"
            "WD_%=:\n\t}"
            :: "r"(bar), "r"(parity) : "memory");
    }
}
__device__ __forceinline__ void ldsm4(uint32_t* r, uint32_t addr) {
    asm volatile("ldmatrix.sync.aligned.m8n8.x4.shared.b16 {%0,%1,%2,%3}, [%4];"
                 : "=r"(r[0]), "=r"(r[1]), "=r"(r[2]), "=r"(r[3]) : "r"(addr));
}
__device__ __forceinline__ void mma_tf32(float* c,
                                         const uint32_t* a,
                                         uint32_t b0, uint32_t b1) {
    asm volatile(
        "mma.sync.aligned.m16n8k8.row.col.f32.tf32.tf32.f32 "
        "{%0,%1,%2,%3}, {%4,%5,%6,%7}, {%8,%9}, {%0,%1,%2,%3};"
        : "+f"(c[0]), "+f"(c[1]), "+f"(c[2]), "+f"(c[3])
        : "r"(a[0]), "r"(a[1]), "r"(a[2]), "r"(a[3]), "r"(b0), "r"(b1));
}

// ---------------- kernel 1: edge MLP (float4) + fused colsum + prep --------
// blocks 0..2047: one A-row each, float4 columns; colsum via atomics
// blocks 2048..2559: tf32-round x
// blocks 2560..2687: W12t
__global__ __launch_bounds__(256) void edge_kernel(
    const float* __restrict__ adj, const float* __restrict__ xdeg,
    const float* __restrict__ ydeg, const float* __restrict__ Wm1,
    const float* __restrict__ bm1, const float* __restrict__ Wm2,
    const float* __restrict__ bm2, const float* __restrict__ x,
    const float* __restrict__ Wg1, const float* __restrict__ Wl2) {
    int b = blockIdx.x;
    int tid = threadIdx.x;
    if (b < NN) {
        __shared__ float sW1[48], sb1[16], sdw[16], sb2[2];
        if (tid < 48) sW1[tid] = Wm1[tid];
        if (tid < 16) sb1[tid] = bm1[tid];
        if (tid < 16) sdw[tid] = Wm2[2 * tid + 1] - Wm2[2 * tid];
        if (tid < 2)  sb2[tid] = bm2[tid];
        int i = b;
        __syncthreads();

        const float4* arow4 = reinterpret_cast<const float4*>(adj  + (size_t)i * NN);
        const float4* xrow4 = reinterpret_cast<const float4*>(xdeg + (size_t)i * NN);
        const float4* yrow4 = reinterpret_cast<const float4*>(ydeg + (size_t)i * NN);
        float4* Arow4 = reinterpret_cast<float4*>(g_A + (size_t)i * NN);
        const float db = sb2[1] - sb2[0];

        float rsum = 0.f;
        float4 csum[2];
        csum[0] = make_float4(0.f, 0.f, 0.f, 0.f);
        csum[1] = make_float4(0.f, 0.f, 0.f, 0.f);

#pragma unroll
        for (int t = 0; t < 2; t++) {
            int j4 = tid + t * 256;            // float4 column group
            float4 a4 = arow4[j4];
            float4 x4 = xrow4[j4];
            float4 y4 = yrow4[j4];
            float av[4] = {a4.x, a4.y, a4.z, a4.w};
            float xv[4] = {x4.x, x4.y, x4.z, x4.w};
            float yv[4] = {y4.x, y4.y, y4.z, y4.w};
            float Ao[4];
#pragma unroll
            for (int c = 0; c < 4; c++) {
                float dl = db;
#pragma unroll
                for (int k = 0; k < MLPW; k++) {
                    float h = fmaf(av[c], sW1[k],
                              fmaf(xv[c], sW1[16 + k],
                              fmaf(yv[c], sW1[32 + k], sb1[k])));
                    h = fmaxf(h, 0.f);
                    dl = fmaf(h, sdw[k], dl);
                }
                float d = 0.5f * dl;
                float th;
                asm("tanh.approx.f32 %0, %1;" : "=f"(th) : "f"(d));
                float mask = fmaf(0.5f, th, 0.5f);
                float Av = av[c] * mask + (j4 * 4 + c == i ? 1.f : 0.f);
                Av = __uint_as_float(f2tf32(Av));
                Ao[c] = Av;
                rsum += Av;
            }
            csum[t].x += Ao[0]; csum[t].y += Ao[1];
            csum[t].z += Ao[2]; csum[t].w += Ao[3];
            Arow4[j4] = make_float4(Ao[0], Ao[1], Ao[2], Ao[3]);
        }
        for (int off = 16; off; off >>= 1) rsum += __shfl_down_sync(0xffffffffu, rsum, off);
        __shared__ float red[8];
        if ((tid & 31) == 0) red[tid >> 5] = rsum;
        __syncthreads();
        if (tid == 0) {
            float s = 0.f;
#pragma unroll
            for (int w = 0; w < 8; w++) s += red[w];
            g_rowsum[i] = s;
        }
        // fused colsum: 8 spread-address atomics per thread
#pragma unroll
        for (int t = 0; t < 2; t++) {
            int j = (tid + t * 256) * 4;
            atomicAdd(&g_colsum[j + 0], csum[t].x);
            atomicAdd(&g_colsum[j + 1], csum[t].y);
            atomicAdd(&g_colsum[j + 2], csum[t].z);
            atomicAdd(&g_colsum[j + 3], csum[t].w);
        }
    } else if (b < NN + 512) {
        size_t idx4 = (size_t)(b - NN) * 1024 + tid;
        const float4* src = reinterpret_cast<const float4*>(x);
        float4* dst = reinterpret_cast<float4*>(g_Xt);
#pragma unroll
        for (int t = 0; t < 4; t++) {
            float4 v = src[idx4 + t * 256];
            uint4 u;
            u.x = f2tf32(v.x); u.y = f2tf32(v.y); u.z = f2tf32(v.z); u.w = f2tf32(v.w);
            dst[idx4 + t * 256] = *reinterpret_cast<float4*>(&u);
        }
    } else {
        // W12t: 128 blocks, each computes rows [rbase, rbase+8) of W12 for all 64 cols
        __shared__ float sW[8][256];
        int rbase = (b - NN - 512) * 8;
#pragma unroll
        for (int t = 0; t < 8; t++) {
            int idx = t * 256 + tid;
            sW[idx >> 8][idx & 255] = Wg1[(size_t)(rbase + (idx >> 8)) * HIDD + (idx & 255)];
        }
        __syncthreads();
        int c = tid & 63, rr = tid >> 6;   // rr 0..3
#pragma unroll
        for (int half = 0; half < 2; half++) {
            int rl = rr + half * 4;
            float acc = 0.f;
#pragma unroll 4
            for (int k = 0; k < HIDD; k++)
                acc = fmaf(sW[rl][k], __ldg(&Wl2[k * L2DIM + c]), acc);
            g_W12t[(size_t)c * IN_DIM + rbase + rl] = __uint_as_float(f2tf32(acc));
        }
    }
}

// ---------------- tf32 tensor-core GEMM, TMA loader, BK=64, 4-stage --------
#define BKK 64
#define HSB 8192      // half-stage bytes per operand (64 rows * 128B)
#define STGB 32768    // full stage (A 16KB + B 16KB)
#define NSTGT 4
#define STG_TX 32768
#define GEMM_SMEM (2048 + NSTGT * STGB)

template <bool TRANSOUT, int NSPLIT, bool SCALE, int CSTRIDE>
__device__ __forceinline__ void gemm_body(const CUtensorMap* mapA,
                                          const CUtensorMap* mapB,
                                          float* __restrict__ C, int Kd,
                                          const float* __restrict__ sumvec) {
    extern __shared__ __align__(16) uint8_t smem_dyn[];
    const uint32_t raw = (uint32_t)__cvta_generic_to_shared(smem_dyn);
    const uint32_t base0 = (raw + 1023u) & ~1023u;   // 1024-aligned for SW128
    const uint32_t barB = base0;                      // 4 mbarriers (8B apart)
    const uint32_t stg0 = base0 + 1024;

    const int tid = threadIdx.x;
    const int lane = tid & 31, warp = tid >> 5;
    const int wm = warp & 1, wn = (warp >> 1) & 1, kg = warp >> 2;  // kg 0..1
    const int gid = lane >> 2, tig = lane & 3;
    const int mi = lane >> 3, lr = lane & 7;
    const int bm0 = blockIdx.y * 64, bn0 = blockIdx.x * 64;
    const int kbase = (NSPLIT > 1) ? blockIdx.z * (Kd / NSPLIT) : 0;

    const int arow = wm * 32 + ((mi & 1) << 3) + lr;
    const int brow = wn * 32 + ((mi >> 1) << 3) + lr;
    const uint32_t axr = arow & 7, bxr = brow & 7;
    const uint32_t qselA = mi >> 1, qselB = mi & 1;
    const uint32_t aOff0 = arow * 128, aOff1 = aOff0 + 16 * 128;
    const uint32_t bOff0 = brow * 128, bOff1 = bOff0 + 16 * 128;
    const uint32_t aqj[2] = {(((uint32_t)(kg * 2 + 0) * 2 + qselA) ^ axr) << 4,
                             (((uint32_t)(kg * 2 + 1) * 2 + qselA) ^ axr) << 4};
    const uint32_t bqj[2] = {(((uint32_t)(kg * 2 + 0) * 2 + qselB) ^ bxr) << 4,
                             (((uint32_t)(kg * 2 + 1) * 2 + qselB) ^ bxr) << 4};

    if (tid == 0) {
#pragma unroll
        for (int s = 0; s < NSTGT; s++) mbar_init(barB + s * 8, 1);
        asm volatile("fence.proxy.async.shared::cta;" ::: "memory");
    }
    __syncthreads();

    auto issue = [&](int kt, int s) {   // tid==0 only
        uint32_t bar = barB + s * 8;
        uint32_t sa = stg0 + s * STGB;
        mbar_expect_tx(bar, STG_TX);
        int k0 = kbase + kt * BKK;
        tma2d(sa,               mapA, k0,      bm0, bar);
        tma2d(sa + HSB,         mapA, k0 + 32, bm0, bar);
        tma2d(sa + 2 * HSB,     mapB, k0,      bn0, bar);
        tma2d(sa + 3 * HSB,     mapB, k0 + 32, bn0, bar);
    };

    const int niter = (Kd / NSPLIT) / BKK;
    if (tid == 0) {
#pragma unroll
        for (int p = 0; p < NSTGT - 1; p++)
            if (p < niter) issue(p, p);
    }

    float acc[2][4][4] = {};
    uint32_t ph[NSTGT] = {};

    for (int i = 0; i < niter; i++) {
        const int s = i & (NSTGT - 1);
        mbar_wait(barB + s * 8, ph[s]);
        ph[s] ^= 1;
        const uint32_t sa = stg0 + s * STGB;
#pragma unroll
        for (int h = 0; h < 2; h++) {
            const uint32_t sAs = sa + h * HSB;
            const uint32_t sBs = sa + 2 * HSB + h * HSB;
#pragma unroll
            for (int jj = 0; jj < 2; jj++) {
                uint32_t af0[4], af1[4], bf0[4], bf1[4];
                ldsm4(af0, sAs + aOff0 + aqj[jj]);
                ldsm4(af1, sAs + aOff1 + aqj[jj]);
                ldsm4(bf0, sBs + bOff0 + bqj[jj]);
                ldsm4(bf1, sBs + bOff1 + bqj[jj]);
                mma_tf32(acc[0][0], af0, bf0[0], bf0[1]);
                mma_tf32(acc[0][1], af0, bf0[2], bf0[3]);
                mma_tf32(acc[0][2], af0, bf1[0], bf1[1]);
                mma_tf32(acc[0][3], af0, bf1[2], bf1[3]);
                mma_tf32(acc[1][0], af1, bf0[0], bf0[1]);
                mma_tf32(acc[1][1], af1, bf0[2], bf0[3]);
                mma_tf32(acc[1][2], af1, bf1[0], bf1[1]);
                mma_tf32(acc[1][3], af1, bf1[2], bf1[3]);
            }
        }
        __syncthreads();   // all warps done with stage s; slot (i-1)%4 now free
        if (i + NSTGT - 1 < niter && tid == 0)
            issue(i + NSTGT - 1, (i + NSTGT - 1) & (NSTGT - 1));
    }

    // ---- 2-way K-split reduction through smem (aliases stage region) ------
    float* sred = reinterpret_cast<float*>(smem_dyn + (stg0 - raw));
    const int pi = wm * 2 + wn;
    if (kg == 1) {
#pragma unroll
        for (int mt = 0; mt < 2; mt++)
#pragma unroll
            for (int nt = 0; nt < 4; nt++) {
                int r = mt * 16 + gid, c = nt * 8 + 2 * tig;
                float* basep = sred + pi * 1056;
                basep[r * 33 + c] = acc[mt][nt][0];
                basep[r * 33 + c + 1] = acc[mt][nt][1];
                basep[(r + 8) * 33 + c] = acc[mt][nt][2];
                basep[(r + 8) * 33 + c + 1] = acc[mt][nt][3];
            }
    }
    __syncthreads();
    if (kg == 0) {
#pragma unroll
        for (int mt = 0; mt < 2; mt++) {
            int r = mt * 16 + gid;
            const float* basep = sred + pi * 1056;
            int gr0 = bm0 + wm * 32 + r;
            int gr1 = gr0 + 8;
            float s0 = SCALE ? rsqrt_pos(sumvec[gr0]) : 1.f;
            float s1 = SCALE ? rsqrt_pos(sumvec[gr1]) : 1.f;
#pragma unroll
            for (int nt = 0; nt < 4; nt++) {
                int c = nt * 8 + 2 * tig;
                float v00 = (acc[mt][nt][0] + basep[r * 33 + c]) * s0;
                float v01 = (acc[mt][nt][1] + basep[r * 33 + c + 1]) * s0;
                float v10 = (acc[mt][nt][2] + basep[(r + 8) * 33 + c]) * s1;
                float v11 = (acc[mt][nt][3] + basep[(r + 8) * 33 + c + 1]) * s1;
                if (TRANSOUT) {
                    int n0 = bn0 + wn * 32 + c;
                    C[(size_t)n0 * NN + gr0] = __uint_as_float(f2tf32(v00));
                    C[(size_t)(n0 + 1) * NN + gr0] = __uint_as_float(f2tf32(v01));
                    C[(size_t)n0 * NN + gr1] = __uint_as_float(f2tf32(v10));
                    C[(size_t)(n0 + 1) * NN + gr1] = __uint_as_float(f2tf32(v11));
                } else {
                    int col = bn0 + wn * 32 + c;
                    *reinterpret_cast<float2*>(&C[(size_t)gr0 * CSTRIDE + col]) =
                        make_float2(v00, v01);
                    *reinterpret_cast<float2*>(&C[(size_t)gr1 * CSTRIDE + col]) =
                        make_float2(v10, v11);
                }
            }
        }
    }
}

// Y: g_Yt = (dc ⊙ (x @ W12))^T [64][2048], tf32; M=2048 N=64 K=1024
__global__ __launch_bounds__(256) void y_kernel(
    const __grid_constant__ CUtensorMap mA, const __grid_constant__ CUtensorMap mB) {
    gemm_body<true, 1, true, 0>(&mA, &mB, g_Yt, IN_DIM, g_colsum);
}
// HID-GEMM: g_Hp[z] = (g_A @ Y) partial over K-quarter z; M=2048 N=64 K=2048
__global__ __launch_bounds__(256) void hidg_kernel(
    const __grid_constant__ CUtensorMap mA, const __grid_constant__ CUtensorMap mB) {
    gemm_body<false, NSPL, false, L2DIM>(&mA, &mB, g_Hp[blockIdx.z], NN, nullptr);
}

// ---------------- finish: hid = dr*sum_z Hp + bl2;  HW = dc*(hid@Wg2) ------
// float4 phase 1; full-width phase 2 (4 threads per output, shfl reduce)
__global__ __launch_bounds__(256) void hid_finish_kernel(const float* __restrict__ bl2,
                                                         const float* __restrict__ Wg2,
                                                         float* __restrict__ hid_out) {
    __shared__ float sHid[16][L2DIM + 4];   // pitch 68 floats (16B-aligned rows)
    int tid = threadIdx.x;
    int rowbase = blockIdx.x * 16;

    int row = tid >> 4;          // 0..15
    int c4 = tid & 15;           // float4 column index
    size_t f4idx = (size_t)rowbase * 16 + tid;

    float4 v = reinterpret_cast<const float4*>(g_Hp[0])[f4idx];
#pragma unroll
    for (int z = 1; z < NSPL; z++) {
        float4 p = reinterpret_cast<const float4*>(g_Hp[z])[f4idx];
        v.x += p.x; v.y += p.y; v.z += p.z; v.w += p.w;
    }
    float dr = rsqrt_pos(g_rowsum[rowbase + row]);
    float4 bias = reinterpret_cast<const float4*>(bl2)[c4];
    v.x = fmaf(v.x, dr, bias.x);
    v.y = fmaf(v.y, dr, bias.y);
    v.z = fmaf(v.z, dr, bias.z);
    v.w = fmaf(v.w, dr, bias.w);
    reinterpret_cast<float4*>(hid_out)[f4idx] = v;
    *reinterpret_cast<float4*>(&sHid[row][c4 * 4]) = v;
    __syncthreads();

    // phase 2: o = (r, cls) output, q = 16-k slice; 4 threads per output
    int q = tid & 3;             // k slice
    int o = tid >> 2;            // 0..63
    int r = o >> 2, cls = o & 3;
    float s = 0.f;
#pragma unroll
    for (int kk = 0; kk < 16; kk++) {
        int k = q * 16 + kk;
        s = fmaf(sHid[r][k], __ldg(&Wg2[k * NCLS + cls]), s);
    }
    s += __shfl_down_sync(0xffffffffu, s, 2);
    s += __shfl_down_sync(0xffffffffu, s, 1);
    if (q == 0)
        g_HW[(size_t)(rowbase + r) * NCLS + cls] = s * rsqrt_pos(g_colsum[rowbase + r]);
}

// ---------------- out[i] = dr[i] * sum_j A[i,j] * HW[j]; re-zero colsum ----
__global__ __launch_bounds__(256) void out_kernel(float* __restrict__ out) {
    int tid = threadIdx.x;
    // restore the colsum==0 invariant for the next graph replay
    if (blockIdx.x == 0) {
#pragma unroll
        for (int t = 0; t < 8; t++) g_colsum[tid + t * 256] = 0.f;
    }
    __shared__ float sHWt[NCLS][NN];
    const float4* hw4 = reinterpret_cast<const float4*>(g_HW);
#pragma unroll
    for (int t = 0; t < NN / 256; t++) {
        int j = tid + t * 256;
        float4 h = hw4[j];            // HW row j: 4 classes
        sHWt[0][j] = h.x; sHWt[1][j] = h.y; sHWt[2][j] = h.z; sHWt[3][j] = h.w;
    }
    __syncthreads();

    const float4* A4 = reinterpret_cast<const float4*>(g_A);
    const int i0 = blockIdx.x * 8;
    float acc[8][4];
#pragma unroll
    for (int r = 0; r < 8; r++)
#pragma unroll
        for (int c = 0; c < 4; c++) acc[r][c] = 0.f;

#pragma unroll
    for (int t = 0; t < NN / 1024; t++) {
        int j4 = tid + t * 256;
        const float4 h0 = *reinterpret_cast<const float4*>(&sHWt[0][j4 * 4]);
        const float4 h1 = *reinterpret_cast<const float4*>(&sHWt[1][j4 * 4]);
        const float4 h2 = *reinterpret_cast<const float4*>(&sHWt[2][j4 * 4]);
        const float4 h3 = *reinterpret_cast<const float4*>(&sHWt[3][j4 * 4]);
#pragma unroll
        for (int r = 0; r < 8; r++) {
            float4 a = A4[(size_t)(i0 + r) * (NN / 4) + j4];
            acc[r][0] += a.x * h0.x + a.y * h0.y + a.z * h0.z + a.w * h0.w;
            acc[r][1] += a.x * h1.x + a.y * h1.y + a.z * h1.z + a.w * h1.w;
            acc[r][2] += a.x * h2.x + a.y * h2.y + a.z * h2.z + a.w * h2.w;
            acc[r][3] += a.x * h3.x + a.y * h3.y + a.z * h3.z + a.w * h3.w;
        }
    }

    __shared__ float red[8][8][4];   // [warp][row][cls]
#pragma unroll
    for (int r = 0; r < 8; r++) {
#pragma unroll
        for (int c = 0; c < 4; c++)
            for (int off = 16; off; off >>= 1)
                acc[r][c] += __shfl_down_sync(0xffffffffu, acc[r][c], off);
        if ((tid & 31) == 0) {
            int w = tid >> 5;
#pragma unroll
            for (int c = 0; c < 4; c++) red[w][r][c] = acc[r][c];
        }
    }
    __syncthreads();
    if (tid < 32) {
        int r = tid >> 2, cls = tid & 3;
        float s = 0.f;
#pragma unroll
        for (int w = 0; w < 8; w++) s += red[w][r][cls];
        out[(i0 + r) * NCLS + cls] = rsqrt_pos(g_rowsum[i0 + r]) * s;
    }
}

// ---------------- host: tensor-map setup + launch --------------------------
typedef CUresult (*PFN_tmEncode)(
    CUtensorMap*, CUtensorMapDataType, cuuint32_t, void*,
    const cuuint64_t*, const cuuint64_t*, const cuuint32_t*, const cuuint32_t*,
    CUtensorMapInterleave, CUtensorMapSwizzle, CUtensorMapL2promotion,
    CUtensorMapFloatOOBfill);

extern "C" void kernel_launch(void* const* d_in, const int* in_sizes, int n_in,
                              void* d_out, int out_size) {
    const float* x    = (const float*)d_in[0];
    const float* adj  = (const float*)d_in[1];
    const float* xdeg = (const float*)d_in[2];
    const float* ydeg = (const float*)d_in[3];
    const float* Wm1  = (const float*)d_in[4];
    const float* bm1  = (const float*)d_in[5];
    const float* Wm2  = (const float*)d_in[6];
    const float* bm2  = (const float*)d_in[7];
    const float* Wg1  = (const float*)d_in[8];
    const float* Wl2  = (const float*)d_in[9];
    const float* bl2  = (const float*)d_in[10];
    const float* Wg2  = (const float*)d_in[11];

    float* out = (float*)d_out;               // [2048, 4]
    float* hid = out + (size_t)NN * NCLS;     // [2048, 64]

    static bool init_done = false;
    static CUtensorMap mA_y, mB_y, mA_h, mB_h;
    if (!init_done) {   // first call is the (uncaptured) correctness run
        cudaFuncSetAttribute(y_kernel,
                             cudaFuncAttributeMaxDynamicSharedMemorySize, GEMM_SMEM);
        cudaFuncSetAttribute(hidg_kernel,
                             cudaFuncAttributeMaxDynamicSharedMemorySize, GEMM_SMEM);
        void* fn = nullptr;
        cudaDriverEntryPointQueryResult qr;
        cudaGetDriverEntryPoint("cuTensorMapEncodeTiled", &fn,
                                cudaEnableDefault, &qr);
        PFN_tmEncode enc = (PFN_tmEncode)fn;
        void *pA, *pXt, *pW12t, *pYt;
        cudaGetSymbolAddress(&pA, g_A);
        cudaGetSymbolAddress(&pXt, g_Xt);
        cudaGetSymbolAddress(&pW12t, g_W12t);
        cudaGetSymbolAddress(&pYt, g_Yt);
        auto mk = [&](CUtensorMap* m, void* ptr, uint64_t d0, uint64_t d1) {
            cuuint64_t dims[2] = {d0, d1};
            cuuint64_t strides[1] = {d0 * 4};
            cuuint32_t box[2] = {32, 64};
            cuuint32_t es[2] = {1, 1};
            enc(m, CU_TENSOR_MAP_DATA_TYPE_FLOAT32, 2, ptr, dims, strides, box, es,
                CU_TENSOR_MAP_INTERLEAVE_NONE, CU_TENSOR_MAP_SWIZZLE_128B,
                CU_TENSOR_MAP_L2_PROMOTION_L2_128B,
                CU_TENSOR_MAP_FLOAT_OOB_FILL_NONE);
        };
        mk(&mA_y, pXt, IN_DIM, NN);
        mk(&mB_y, pW12t, IN_DIM, L2DIM);
        mk(&mA_h, pA, NN, NN);
        mk(&mB_h, pYt, NN, L2DIM);
        init_done = true;
    }

    edge_kernel<<<NN + 512 + 128, 256>>>(adj, xdeg, ydeg, Wm1, bm1, Wm2, bm2,
                                         x, Wg1, Wl2);
    y_kernel<<<dim3(1, NN / 64, 1), 256, GEMM_SMEM>>>(mA_y, mB_y);
    hidg_kernel<<<dim3(1, NN / 64, NSPL), 256, GEMM_SMEM>>>(mA_h, mB_h);
    hid_finish_kernel<<<NN / 16, 256>>>(bl2, Wg2, hid);
    out_kernel<<<NN / 8, 256>>>(out);
}